// round 6
// baseline (speedup 1.0000x reference)
#include <cuda_runtime.h>
#include <math.h>

#define NMID 500000
#define DD 64
#define KI 4
#define CC 512
#define SS 256
#define BB 512
#define NEGV (-4294967295.0f)
#define FMIN2 (-3.402823466e38f)

#define IST 68
#define QST 264
#define SST 260
// dynamic smem floats: items 17408 | qT 16896 | sc 16640 | mask 256 | col 64 | mean 64
#define SM_FLOATS 51328

__device__ float g_wmean[KI*DD];
__device__ float g_posSum[DD];
__device__ float g_cand0[CC*DD];
__device__ float g_cand[CC*DD];
__device__ float g_candW4[CC*DD];
__device__ float g_transT[(size_t)CC*CC];
__device__ float g_seq[(size_t)BB*SS*DD];

// ---------------- K0: zero wmean, pos column sums ----------------
__global__ void k_pre(const float* __restrict__ pos) {
    int t = threadIdx.x;
    if (t < KI*DD) g_wmean[t] = 0.f;
    if (t < DD) {
        float s = 0.f;
        for (int i = 0; i < SS; i++) s += pos[i*DD + t];
        g_posSum[t] = s;
    }
}

// ---------------- K1: wmean[k,d] = sum_n (E[n]. W2[k]) * E[n,d] ----------------
__global__ void k_wmean(const float* __restrict__ E, const float* __restrict__ W2) {
    __shared__ float red[8*256];
    int t = threadIdx.x, l = t & 31, wi = t >> 5;
    int gw = (blockIdx.x*blockDim.x + t) >> 5;
    int TW = (gridDim.x*blockDim.x) >> 5;
    float2 w2[KI];
#pragma unroll
    for (int k = 0; k < KI; k++) {
        w2[k].x = W2[k*DD + 2*l];
        w2[k].y = W2[k*DD + 2*l + 1];
    }
    float2 acc[KI];
#pragma unroll
    for (int k = 0; k < KI; k++) acc[k] = make_float2(0.f, 0.f);
    const float2* E2 = (const float2*)E;
    for (long n = gw; n < NMID; n += TW) {
        float2 e = E2[n*32 + l];
#pragma unroll
        for (int k = 0; k < KI; k++) {
            float p = fmaf(e.x, w2[k].x, e.y*w2[k].y);
#pragma unroll
            for (int o = 16; o; o >>= 1) p += __shfl_xor_sync(~0u, p, o);
            acc[k].x = fmaf(p, e.x, acc[k].x);
            acc[k].y = fmaf(p, e.y, acc[k].y);
        }
    }
#pragma unroll
    for (int k = 0; k < KI; k++) {
        red[wi*256 + k*64 + 2*l]     = acc[k].x;
        red[wi*256 + k*64 + 2*l + 1] = acc[k].y;
    }
    __syncthreads();
    if (t < 256) {
        float s = 0.f;
#pragma unroll
        for (int w = 0; w < 8; w++) s += red[w*256 + t];
        atomicAdd(&g_wmean[t], s);
    }
}

// ---------------- K2: cand0, cand=tanh(cand0@W1), candW4=cand0@W4 ----------------
__global__ void k_cand(const float* __restrict__ W3, const float* __restrict__ W1,
                       const float* __restrict__ W4) {
    __shared__ float row[DD];
    int d = threadIdx.x, c = blockIdx.x;
    float v = 0.f;
#pragma unroll
    for (int k = 0; k < KI; k++) v = fmaf(W3[k*CC + c], g_wmean[k*DD + d], v);
    row[d] = v;
    g_cand0[c*DD + d] = v;
    __syncthreads();
    float a = 0.f, bv = 0.f;
#pragma unroll 8
    for (int e = 0; e < DD; e++) {
        float r = row[e];
        a  = fmaf(r, W1[e*DD + d], a);
        bv = fmaf(r, W4[e*DD + d], bv);
    }
    g_cand[c*DD + d]   = tanhf(a);
    g_candW4[c*DD + d] = bv;
}

// ---------------- K3: transT[j][i] = softmax_i( candW4[i] . cand0[j] ) ----------------
__global__ void k_trans() {
    __shared__ float c0j[DD];
    __shared__ float red[8];
    __shared__ float bmax, bsum;
    int t = threadIdx.x, j = blockIdx.x, w = t >> 5, l = t & 31;
    if (t < DD) c0j[t] = g_cand0[j*DD + t];
    __syncthreads();
    float v0 = 0.f, v1 = 0.f;
    {
        const float4* r4 = (const float4*)(g_candW4 + (size_t)t*DD);
#pragma unroll
        for (int e4 = 0; e4 < 16; e4++) {
            float4 q = r4[e4];
            v0 = fmaf(q.x, c0j[4*e4], v0);   v0 = fmaf(q.y, c0j[4*e4+1], v0);
            v0 = fmaf(q.z, c0j[4*e4+2], v0); v0 = fmaf(q.w, c0j[4*e4+3], v0);
        }
        r4 = (const float4*)(g_candW4 + (size_t)(t+256)*DD);
#pragma unroll
        for (int e4 = 0; e4 < 16; e4++) {
            float4 q = r4[e4];
            v1 = fmaf(q.x, c0j[4*e4], v1);   v1 = fmaf(q.y, c0j[4*e4+1], v1);
            v1 = fmaf(q.z, c0j[4*e4+2], v1); v1 = fmaf(q.w, c0j[4*e4+3], v1);
        }
    }
    float m = fmaxf(v0, v1);
#pragma unroll
    for (int o = 16; o; o >>= 1) m = fmaxf(m, __shfl_xor_sync(~0u, m, o));
    if (l == 0) red[w] = m;
    __syncthreads();
    if (t == 0) { float mm = red[0]; for (int i = 1; i < 8; i++) mm = fmaxf(mm, red[i]); bmax = mm; }
    __syncthreads();
    float p0 = expf(v0 - bmax), p1 = expf(v1 - bmax);
    float s = p0 + p1;
#pragma unroll
    for (int o = 16; o; o >>= 1) s += __shfl_xor_sync(~0u, s, o);
    if (l == 0) red[w] = s;
    __syncthreads();
    if (t == 0) { float ss = 0.f; for (int i = 0; i < 8; i++) ss += red[i]; bsum = ss; }
    __syncthreads();
    float inv = 1.f / bsum;
    g_transT[(size_t)j*CC + t]       = p0 * inv;
    g_transT[(size_t)j*CC + t + 256] = p1 * inv;
}

// ---------------- K4: per-batch fused everything ----------------
__global__ void __launch_bounds__(256,1) k_att(
    const float* __restrict__ E, const float* __restrict__ W1,
    const float* __restrict__ pos, const float* __restrict__ dw,
    const float* __restrict__ db, const int* __restrict__ his,
    const int* __restrict__ mask, const int* __restrict__ midb,
    float* __restrict__ out, long out_size)
{
    extern __shared__ float sm[];
    float* itemsS = sm;              // 256 x 68
    float* qT     = sm + 17408;      // 64 x 264
    float* sc     = sm + 34304;      // 64 x 260 (multi-use)
    float* maskS  = sm + 50944;      // 256
    float* colS   = sm + 51200;      // 64
    float* meanS  = sm + 51264;      // 64
    __shared__ float sDen;
    __shared__ float rv[8]; __shared__ int riS[8];
    __shared__ int idxS[4]; __shared__ float itemS[64];
    __shared__ float dotS[4]; __shared__ int ridxS;

    int b = blockIdx.x, t = threadIdx.x, w = t >> 5, l = t & 31;

    // ---- A: loads ----
    if (t < SS) maskS[t] = (float)mask[b*SS + t];
    if (t < 64) colS[t] = 0.f;
    {
        float* dwS = sc; float* biasS = sc + 4096;
        for (int i = t; i < 4096; i += 256) dwS[i] = dw[i];
        if (t < 64) biasS[t] = db[t];
        if (t < 64) itemS[t] = E[(size_t)midb[b]*DD + t];
    }
    {
        const float4* E4 = (const float4*)E;
        float4* it4 = (float4*)itemsS;
        const int* hr = his + b*SS;
        for (int f = t; f < SS*16; f += 256) {
            int s = f >> 4, c = f & 15;
            it4[s*17 + c] = E4[(size_t)hr[s]*16 + c];
        }
    }
    __syncthreads();
    if (w == 0) {
        float s = 0.f;
        for (int i = l; i < SS; i += 32) s += maskS[i];
#pragma unroll
        for (int o = 16; o; o >>= 1) s += __shfl_xor_sync(~0u, s, o);
        if (l == 0) sDen = 1.f / (s + 1e-9f);
    }

    // ---- B: qT[d][s] = tanh((items+pos) @ dense_w + b) ----
    {
        float* dwS = sc; float* biasS = sc + 4096;
        float x[64];
#pragma unroll 16
        for (int e = 0; e < 64; e++) x[e] = itemsS[t*IST + e] + pos[t*DD + e];
        for (int d = 0; d < 64; d += 4) {
            float a0 = biasS[d], a1 = biasS[d+1], a2 = biasS[d+2], a3 = biasS[d+3];
#pragma unroll 16
            for (int e = 0; e < 64; e++) {
                float4 wv = *(const float4*)&dwS[e*64 + d];
                float xe = x[e];
                a0 = fmaf(xe, wv.x, a0); a1 = fmaf(xe, wv.y, a1);
                a2 = fmaf(xe, wv.z, a2); a3 = fmaf(xe, wv.w, a3);
            }
            qT[d*QST + t]     = tanhf(a0);
            qT[(d+1)*QST + t] = tanhf(a1);
            qT[(d+2)*QST + t] = tanhf(a2);
            qT[(d+3)*QST + t] = tanhf(a3);
        }
    }
    __syncthreads();

    // ---- C: scores -> softmax -> seq (4 groups of 64 query rows) ----
    int ty = t >> 4, tx = t & 15;
    float rs0 = 0.f, rs1 = 0.f, rs2 = 0.f, rs3 = 0.f;
    for (int g = 0; g < 4; g++) {
        int s0 = g*64;
        for (int kt = 0; kt < 4; kt++) {
            int k0 = kt*64;
            float acc[4][4];
#pragma unroll
            for (int i = 0; i < 4; i++)
#pragma unroll
                for (int j = 0; j < 4; j++) acc[i][j] = 0.f;
#pragma unroll 4
            for (int e = 0; e < 64; e++) {
                float4 a  = *(const float4*)&qT[e*QST + s0 + 4*ty];
                float4 bb = *(const float4*)&qT[e*QST + k0 + 4*tx];
                acc[0][0]=fmaf(a.x,bb.x,acc[0][0]); acc[0][1]=fmaf(a.x,bb.y,acc[0][1]);
                acc[0][2]=fmaf(a.x,bb.z,acc[0][2]); acc[0][3]=fmaf(a.x,bb.w,acc[0][3]);
                acc[1][0]=fmaf(a.y,bb.x,acc[1][0]); acc[1][1]=fmaf(a.y,bb.y,acc[1][1]);
                acc[1][2]=fmaf(a.y,bb.z,acc[1][2]); acc[1][3]=fmaf(a.y,bb.w,acc[1][3]);
                acc[2][0]=fmaf(a.z,bb.x,acc[2][0]); acc[2][1]=fmaf(a.z,bb.y,acc[2][1]);
                acc[2][2]=fmaf(a.z,bb.z,acc[2][2]); acc[2][3]=fmaf(a.z,bb.w,acc[2][3]);
                acc[3][0]=fmaf(a.w,bb.x,acc[3][0]); acc[3][1]=fmaf(a.w,bb.y,acc[3][1]);
                acc[3][2]=fmaf(a.w,bb.z,acc[3][2]); acc[3][3]=fmaf(a.w,bb.w,acc[3][3]);
            }
#pragma unroll
            for (int i = 0; i < 4; i++)
                *(float4*)&sc[(4*ty+i)*SST + k0 + 4*tx] =
                    make_float4(acc[i][0], acc[i][1], acc[i][2], acc[i][3]);
        }
        __syncthreads();
        for (int rr = w; rr < 64; rr += 8) {
            int s = s0 + rr;
            if (maskS[s] == 0.f) {
                for (int c = l; c < 256; c += 32) sc[rr*SST + c] = 0.f;
            } else {
                float v[8]; float mx = FMIN2;
#pragma unroll
                for (int c = 0; c < 8; c++) {
                    float rawv = sc[rr*SST + l + 32*c] * 0.125f;
                    if (maskS[l + 32*c] == 0.f) rawv = NEGV;
                    v[c] = rawv; mx = fmaxf(mx, rawv);
                }
#pragma unroll
                for (int o = 16; o; o >>= 1) mx = fmaxf(mx, __shfl_xor_sync(~0u, mx, o));
                float sum = 0.f;
#pragma unroll
                for (int c = 0; c < 8; c++) { v[c] = expf(v[c] - mx); sum += v[c]; }
#pragma unroll
                for (int o = 16; o; o >>= 1) sum += __shfl_xor_sync(~0u, sum, o);
                float inv = 1.f / sum;
#pragma unroll
                for (int c = 0; c < 8; c++) sc[rr*SST + l + 32*c] = v[c]*inv;
            }
        }
        __syncthreads();
        {
            float acc[4][4];
#pragma unroll
            for (int i = 0; i < 4; i++)
#pragma unroll
                for (int j = 0; j < 4; j++) acc[i][j] = 0.f;
            const float* ar = sc + 4*ty*SST;
#pragma unroll 2
            for (int k = 0; k < 256; k++) {
                float4 bv = *(const float4*)&itemsS[k*IST + 4*tx];
                float a0 = ar[k], a1 = ar[SST+k], a2 = ar[2*SST+k], a3 = ar[3*SST+k];
                acc[0][0]=fmaf(a0,bv.x,acc[0][0]); acc[0][1]=fmaf(a0,bv.y,acc[0][1]);
                acc[0][2]=fmaf(a0,bv.z,acc[0][2]); acc[0][3]=fmaf(a0,bv.w,acc[0][3]);
                acc[1][0]=fmaf(a1,bv.x,acc[1][0]); acc[1][1]=fmaf(a1,bv.y,acc[1][1]);
                acc[1][2]=fmaf(a1,bv.z,acc[1][2]); acc[1][3]=fmaf(a1,bv.w,acc[1][3]);
                acc[2][0]=fmaf(a2,bv.x,acc[2][0]); acc[2][1]=fmaf(a2,bv.y,acc[2][1]);
                acc[2][2]=fmaf(a2,bv.z,acc[2][2]); acc[2][3]=fmaf(a2,bv.w,acc[2][3]);
                acc[3][0]=fmaf(a3,bv.x,acc[3][0]); acc[3][1]=fmaf(a3,bv.y,acc[3][1]);
                acc[3][2]=fmaf(a3,bv.z,acc[3][2]); acc[3][3]=fmaf(a3,bv.w,acc[3][3]);
            }
            float* so = &g_seq[((size_t)b*SS + s0 + 4*ty)*DD + 4*tx];
#pragma unroll
            for (int i = 0; i < 4; i++) {
                *(float4*)(so + (size_t)i*DD) =
                    make_float4(acc[i][0], acc[i][1], acc[i][2], acc[i][3]);
                rs0 += acc[i][0]; rs1 += acc[i][1]; rs2 += acc[i][2]; rs3 += acc[i][3];
            }
        }
        __syncthreads();
    }
    atomicAdd(&colS[4*tx],   rs0);
    atomicAdd(&colS[4*tx+1], rs1);
    atomicAdd(&colS[4*tx+2], rs2);
    atomicAdd(&colS[4*tx+3], rs3);
    __syncthreads();

    // ---- mean_h, logits, logits@trans, top-4 ----
    float* W1S = sc; float* logitsS = sc + 4096; float* mhS = sc + 4608;
    float* wrS = sc + 4672; float* aqS = sc + 5712; float* uebS = sc + 5968;
    for (int i = t; i < 4096; i += 256) W1S[i] = W1[i];
    __syncthreads();
    if (t < 64) meanS[t] = (colS[t] + g_posSum[t]) * sDen;
    __syncthreads();
    if (t < 64) {
        float a = 0.f;
#pragma unroll 16
        for (int e = 0; e < 64; e++) a = fmaf(meanS[e], W1S[e*64 + t], a);
        mhS[t] = tanhf(a);
    }
    __syncthreads();
    for (int c = t; c < 512; c += 256) {
        const float4* cr = (const float4*)&g_cand[c*64];
        float a = 0.f;
#pragma unroll
        for (int e4 = 0; e4 < 16; e4++) {
            float4 cv = cr[e4];
            a = fmaf(cv.x, mhS[4*e4], a);   a = fmaf(cv.y, mhS[4*e4+1], a);
            a = fmaf(cv.z, mhS[4*e4+2], a); a = fmaf(cv.w, mhS[4*e4+3], a);
        }
        logitsS[c] = a;
    }
    __syncthreads();
    float lg0, lg1;
    {
        const float4* tr = (const float4*)&g_transT[(size_t)t*CC];
        float a = 0.f;
#pragma unroll 8
        for (int i4 = 0; i4 < 128; i4++) {
            float4 tv = tr[i4];
            a = fmaf(tv.x, logitsS[4*i4], a);   a = fmaf(tv.y, logitsS[4*i4+1], a);
            a = fmaf(tv.z, logitsS[4*i4+2], a); a = fmaf(tv.w, logitsS[4*i4+3], a);
        }
        lg0 = a;
        tr = (const float4*)&g_transT[(size_t)(t+256)*CC];
        a = 0.f;
#pragma unroll 8
        for (int i4 = 0; i4 < 128; i4++) {
            float4 tv = tr[i4];
            a = fmaf(tv.x, logitsS[4*i4], a);   a = fmaf(tv.y, logitsS[4*i4+1], a);
            a = fmaf(tv.z, logitsS[4*i4+2], a); a = fmaf(tv.w, logitsS[4*i4+3], a);
        }
        lg1 = a;
    }
    __syncthreads();
    logitsS[t] = lg0; logitsS[t+256] = lg1;
    __syncthreads();
    for (int p = 0; p < 4; p++) {
        float bv = logitsS[t]; int bi = t;
        float v2 = logitsS[t+256];
        if (v2 > bv) { bv = v2; bi = t+256; }
#pragma unroll
        for (int o = 16; o; o >>= 1) {
            float ov = __shfl_xor_sync(~0u, bv, o);
            int   oi = __shfl_xor_sync(~0u, bi, o);
            if (ov > bv || (ov == bv && oi < bi)) { bv = ov; bi = oi; }
        }
        if (l == 0) { rv[w] = bv; riS[w] = bi; }
        __syncthreads();
        if (t == 0) {
            float B2 = rv[0]; int BI = riS[0];
            for (int i = 1; i < 8; i++)
                if (rv[i] > B2 || (rv[i] == B2 && riS[i] < BI)) { B2 = rv[i]; BI = riS[i]; }
            idxS[p] = BI; logitsS[BI] = FMIN2;
        }
        __syncthreads();
    }
    { int k = t >> 6, d = t & 63; aqS[t] = g_cand[(size_t)idxS[k]*64 + d]; }
    __syncthreads();

    // ---- D: multi-interest attention ----
    {
        float x[64];
        const float* sr = &g_seq[((size_t)b*SS + t)*DD];
#pragma unroll 16
        for (int e = 0; e < 64; e++) x[e] = sr[e] + pos[t*DD + e];
        float wv0 = 0.f, wv1 = 0.f, wv2 = 0.f, wv3 = 0.f;
        for (int d = 0; d < 64; d += 4) {
            float a0 = 0.f, a1 = 0.f, a2 = 0.f, a3 = 0.f;
#pragma unroll 16
            for (int e = 0; e < 64; e++) {
                float4 w4 = *(const float4*)&W1S[e*64 + d];
                float xe = x[e];
                a0 = fmaf(xe, w4.x, a0); a1 = fmaf(xe, w4.y, a1);
                a2 = fmaf(xe, w4.z, a2); a3 = fmaf(xe, w4.w, a3);
            }
            a0 = tanhf(a0); a1 = tanhf(a1); a2 = tanhf(a2); a3 = tanhf(a3);
            float4 q0 = *(const float4*)&aqS[0*64 + d];
            float4 q1 = *(const float4*)&aqS[1*64 + d];
            float4 q2 = *(const float4*)&aqS[2*64 + d];
            float4 q3 = *(const float4*)&aqS[3*64 + d];
            wv0 += fmaf(a0,q0.x, fmaf(a1,q0.y, fmaf(a2,q0.z, a3*q0.w)));
            wv1 += fmaf(a0,q1.x, fmaf(a1,q1.y, fmaf(a2,q1.z, a3*q1.w)));
            wv2 += fmaf(a0,q2.x, fmaf(a1,q2.y, fmaf(a2,q2.z, a3*q2.w)));
            wv3 += fmaf(a0,q3.x, fmaf(a1,q3.y, fmaf(a2,q3.z, a3*q3.w)));
        }
        float m = maskS[t];
        wrS[0*260 + t] = (m == 0.f) ? NEGV : wv0;
        wrS[1*260 + t] = (m == 0.f) ? NEGV : wv1;
        wrS[2*260 + t] = (m == 0.f) ? NEGV : wv2;
        wrS[3*260 + t] = (m == 0.f) ? NEGV : wv3;
    }
    __syncthreads();
    if (w < 4) {
        float v[8]; float mx = FMIN2;
#pragma unroll
        for (int c = 0; c < 8; c++) { v[c] = wrS[w*260 + l + 32*c]; mx = fmaxf(mx, v[c]); }
#pragma unroll
        for (int o = 16; o; o >>= 1) mx = fmaxf(mx, __shfl_xor_sync(~0u, mx, o));
        float sum = 0.f;
#pragma unroll
        for (int c = 0; c < 8; c++) { v[c] = expf(v[c] - mx); sum += v[c]; }
#pragma unroll
        for (int o = 16; o; o >>= 1) sum += __shfl_xor_sync(~0u, sum, o);
        float inv = 1.f / sum;
#pragma unroll
        for (int c = 0; c < 8; c++) wrS[w*260 + l + 32*c] = v[c]*inv;
    }
    __syncthreads();
    {
        int k = t >> 6, d = t & 63;
        const float* wp = &wrS[k*260];
        const float* sp = &g_seq[(size_t)b*SS*DD + d];
        float a = 0.f;
#pragma unroll 8
        for (int s = 0; s < 256; s++) a = fmaf(wp[s], sp[(size_t)s*64], a);
        uebS[t] = a;
        long off = 32768 + (long)b*256 + t;
        if (off < out_size) out[off] = a;
    }
    __syncthreads();
    if (w < 4) {
        float p = uebS[w*64 + l]*itemS[l] + uebS[w*64 + l + 32]*itemS[l + 32];
#pragma unroll
        for (int o = 16; o; o >>= 1) p += __shfl_xor_sync(~0u, p, o);
        if (l == 0) dotS[w] = p;
    }
    __syncthreads();
    if (t == 0) {
        float bv2 = dotS[0]; int bi2 = 0;
        for (int k = 1; k < 4; k++) if (dotS[k] > bv2) { bv2 = dotS[k]; bi2 = k; }
        ridxS = bi2;
    }
    __syncthreads();
    if (t < 64) {
        long off = (long)b*64 + t;
        if (off < out_size) out[off] = uebS[ridxS*64 + t];
    }
    if (t < 4) {
        long off = 163840 + (long)b*4 + t;
        if (off < out_size) out[off] = (float)idxS[t];
    }
}

extern "C" void kernel_launch(void* const* d_in, const int* in_sizes, int n_in,
                              void* d_out, int out_size) {
    const float* E    = (const float*)d_in[0];
    const float* W1   = (const float*)d_in[1];
    const float* W2   = (const float*)d_in[2];
    const float* W3   = (const float*)d_in[3];
    const float* W4   = (const float*)d_in[4];
    const float* pos  = (const float*)d_in[5];
    const float* dw   = (const float*)d_in[6];
    const float* db   = (const float*)d_in[7];
    const int*   his  = (const int*)d_in[8];
    const int*   mask = (const int*)d_in[9];
    const int*   midb = (const int*)d_in[10];
    float* out = (float*)d_out;

    cudaFuncSetAttribute(k_att, cudaFuncAttributeMaxDynamicSharedMemorySize,
                         SM_FLOATS * (int)sizeof(float));

    k_pre<<<1, 256>>>(pos);
    k_wmean<<<1184, 256>>>(E, W2);
    k_cand<<<CC, DD>>>(W3, W1, W4);
    k_trans<<<CC, 256>>>();
    k_att<<<BB, 256, SM_FLOATS * sizeof(float)>>>(E, W1, pos, dw, db,
                                                  his, mask, midb,
                                                  out, (long)out_size);
}

// round 7
// speedup vs baseline: 1.0003x; 1.0003x over previous
#include <cuda_runtime.h>
#include <math.h>

#define NMID 500000
#define DD 64
#define KI 4
#define CC 512
#define SS 256
#define BB 512
#define NEGV (-4294967295.0f)
#define FMIN2 (-3.402823466e38f)

#define IST 68
#define QST 264
#define SST 260
// dynamic smem floats: items 17408 | qT 16896 | sc 16640 | mask 256 | col 64 | mean 64
#define SM_FLOATS 51328

__device__ float g_wmean[KI*DD];
__device__ float g_posSum[DD];
__device__ float g_cand0[CC*DD];
__device__ float g_cand[CC*DD];
__device__ float g_candW4[CC*DD];
__device__ float g_transT[(size_t)CC*CC];
__device__ float g_seq[(size_t)BB*SS*DD];

// ---------------- K0: zero wmean, pos column sums ----------------
__global__ void k_pre(const float* __restrict__ pos) {
    int t = threadIdx.x;
    if (t < KI*DD) g_wmean[t] = 0.f;
    if (t < DD) {
        float s = 0.f;
        for (int i = 0; i < SS; i++) s += pos[i*DD + t];
        g_posSum[t] = s;
    }
}

// ---------------- K1: wmean[k,d] = sum_n (E[n]. W2[k]) * E[n,d] ----------------
__global__ void k_wmean(const float* __restrict__ E, const float* __restrict__ W2) {
    __shared__ float red[8*256];
    int t = threadIdx.x, l = t & 31, wi = t >> 5;
    int gw = (blockIdx.x*blockDim.x + t) >> 5;
    int TW = (gridDim.x*blockDim.x) >> 5;
    float2 w2[KI];
#pragma unroll
    for (int k = 0; k < KI; k++) {
        w2[k].x = W2[k*DD + 2*l];
        w2[k].y = W2[k*DD + 2*l + 1];
    }
    float2 acc[KI];
#pragma unroll
    for (int k = 0; k < KI; k++) acc[k] = make_float2(0.f, 0.f);
    const float2* E2 = (const float2*)E;
    for (long n = gw; n < NMID; n += TW) {
        float2 e = E2[n*32 + l];
#pragma unroll
        for (int k = 0; k < KI; k++) {
            float p = fmaf(e.x, w2[k].x, e.y*w2[k].y);
#pragma unroll
            for (int o = 16; o; o >>= 1) p += __shfl_xor_sync(~0u, p, o);
            acc[k].x = fmaf(p, e.x, acc[k].x);
            acc[k].y = fmaf(p, e.y, acc[k].y);
        }
    }
#pragma unroll
    for (int k = 0; k < KI; k++) {
        red[wi*256 + k*64 + 2*l]     = acc[k].x;
        red[wi*256 + k*64 + 2*l + 1] = acc[k].y;
    }
    __syncthreads();
    if (t < 256) {
        float s = 0.f;
#pragma unroll
        for (int w = 0; w < 8; w++) s += red[w*256 + t];
        atomicAdd(&g_wmean[t], s);
    }
}

// ---------------- K2: cand0, cand=tanh(cand0@W1), candW4=cand0@W4 ----------------
__global__ void k_cand(const float* __restrict__ W3, const float* __restrict__ W1,
                       const float* __restrict__ W4) {
    __shared__ float row[DD];
    int d = threadIdx.x, c = blockIdx.x;
    float v = 0.f;
#pragma unroll
    for (int k = 0; k < KI; k++) v = fmaf(W3[k*CC + c], g_wmean[k*DD + d], v);
    row[d] = v;
    g_cand0[c*DD + d] = v;
    __syncthreads();
    float a = 0.f, bv = 0.f;
#pragma unroll 8
    for (int e = 0; e < DD; e++) {
        float r = row[e];
        a  = fmaf(r, W1[e*DD + d], a);
        bv = fmaf(r, W4[e*DD + d], bv);
    }
    g_cand[c*DD + d]   = tanhf(a);
    g_candW4[c*DD + d] = bv;
}

// ---------------- K3: transT[j][i] = softmax_i( candW4[i] . cand0[j] ) ----------------
__global__ void k_trans() {
    __shared__ float c0j[DD];
    __shared__ float red[8];
    __shared__ float bmax, bsum;
    int t = threadIdx.x, j = blockIdx.x, w = t >> 5, l = t & 31;
    if (t < DD) c0j[t] = g_cand0[j*DD + t];
    __syncthreads();
    float v0 = 0.f, v1 = 0.f;
    {
        const float4* r4 = (const float4*)(g_candW4 + (size_t)t*DD);
#pragma unroll
        for (int e4 = 0; e4 < 16; e4++) {
            float4 q = r4[e4];
            v0 = fmaf(q.x, c0j[4*e4], v0);   v0 = fmaf(q.y, c0j[4*e4+1], v0);
            v0 = fmaf(q.z, c0j[4*e4+2], v0); v0 = fmaf(q.w, c0j[4*e4+3], v0);
        }
        r4 = (const float4*)(g_candW4 + (size_t)(t+256)*DD);
#pragma unroll
        for (int e4 = 0; e4 < 16; e4++) {
            float4 q = r4[e4];
            v1 = fmaf(q.x, c0j[4*e4], v1);   v1 = fmaf(q.y, c0j[4*e4+1], v1);
            v1 = fmaf(q.z, c0j[4*e4+2], v1); v1 = fmaf(q.w, c0j[4*e4+3], v1);
        }
    }
    float m = fmaxf(v0, v1);
#pragma unroll
    for (int o = 16; o; o >>= 1) m = fmaxf(m, __shfl_xor_sync(~0u, m, o));
    if (l == 0) red[w] = m;
    __syncthreads();
    if (t == 0) { float mm = red[0]; for (int i = 1; i < 8; i++) mm = fmaxf(mm, red[i]); bmax = mm; }
    __syncthreads();
    float p0 = expf(v0 - bmax), p1 = expf(v1 - bmax);
    float s = p0 + p1;
#pragma unroll
    for (int o = 16; o; o >>= 1) s += __shfl_xor_sync(~0u, s, o);
    if (l == 0) red[w] = s;
    __syncthreads();
    if (t == 0) { float ss = 0.f; for (int i = 0; i < 8; i++) ss += red[i]; bsum = ss; }
    __syncthreads();
    float inv = 1.f / bsum;
    g_transT[(size_t)j*CC + t]       = p0 * inv;
    g_transT[(size_t)j*CC + t + 256] = p1 * inv;
}

// ---------------- K4: per-batch fused everything ----------------
__global__ void __launch_bounds__(256,1) k_att(
    const float* __restrict__ E, const float* __restrict__ W1,
    const float* __restrict__ pos, const float* __restrict__ dw,
    const float* __restrict__ db, const int* __restrict__ his,
    const int* __restrict__ mask, const int* __restrict__ midb,
    float* __restrict__ out, long out_size)
{
    extern __shared__ float sm[];
    float* itemsS = sm;              // 256 x 68
    float* qT     = sm + 17408;      // 64 x 264
    float* sc     = sm + 34304;      // 64 x 260 (multi-use)
    float* maskS  = sm + 50944;      // 256
    float* colS   = sm + 51200;      // 64
    float* meanS  = sm + 51264;      // 64
    __shared__ float sDen;
    __shared__ float rv[8]; __shared__ int riS[8];
    __shared__ int idxS[4]; __shared__ float itemS[64];
    __shared__ float dotS[4]; __shared__ int ridxS;

    int b = blockIdx.x, t = threadIdx.x, w = t >> 5, l = t & 31;

    // ---- A: loads ----
    if (t < SS) maskS[t] = (float)mask[b*SS + t];
    if (t < 64) colS[t] = 0.f;
    {
        float* dwS = sc; float* biasS = sc + 4096;
        for (int i = t; i < 4096; i += 256) dwS[i] = dw[i];
        if (t < 64) biasS[t] = db[t];
        if (t < 64) itemS[t] = E[(size_t)midb[b]*DD + t];
    }
    {
        const float4* E4 = (const float4*)E;
        float4* it4 = (float4*)itemsS;
        const int* hr = his + b*SS;
        for (int f = t; f < SS*16; f += 256) {
            int s = f >> 4, c = f & 15;
            it4[s*17 + c] = E4[(size_t)hr[s]*16 + c];
        }
    }
    __syncthreads();
    if (w == 0) {
        float s = 0.f;
        for (int i = l; i < SS; i += 32) s += maskS[i];
#pragma unroll
        for (int o = 16; o; o >>= 1) s += __shfl_xor_sync(~0u, s, o);
        if (l == 0) sDen = 1.f / (s + 1e-9f);
    }

    // ---- B: qT[d][s] = tanh((items+pos) @ dense_w + b) ----
    {
        float* dwS = sc; float* biasS = sc + 4096;
        float x[64];
#pragma unroll 16
        for (int e = 0; e < 64; e++) x[e] = itemsS[t*IST + e] + pos[t*DD + e];
        for (int d = 0; d < 64; d += 4) {
            float a0 = biasS[d], a1 = biasS[d+1], a2 = biasS[d+2], a3 = biasS[d+3];
#pragma unroll 16
            for (int e = 0; e < 64; e++) {
                float4 wv = *(const float4*)&dwS[e*64 + d];
                float xe = x[e];
                a0 = fmaf(xe, wv.x, a0); a1 = fmaf(xe, wv.y, a1);
                a2 = fmaf(xe, wv.z, a2); a3 = fmaf(xe, wv.w, a3);
            }
            qT[d*QST + t]     = tanhf(a0);
            qT[(d+1)*QST + t] = tanhf(a1);
            qT[(d+2)*QST + t] = tanhf(a2);
            qT[(d+3)*QST + t] = tanhf(a3);
        }
    }
    __syncthreads();

    // ---- C: scores -> softmax -> seq (4 groups of 64 query rows) ----
    int ty = t >> 4, tx = t & 15;
    float rs0 = 0.f, rs1 = 0.f, rs2 = 0.f, rs3 = 0.f;
    for (int g = 0; g < 4; g++) {
        int s0 = g*64;
        for (int kt = 0; kt < 4; kt++) {
            int k0 = kt*64;
            float acc[4][4];
#pragma unroll
            for (int i = 0; i < 4; i++)
#pragma unroll
                for (int j = 0; j < 4; j++) acc[i][j] = 0.f;
#pragma unroll 4
            for (int e = 0; e < 64; e++) {
                float4 a  = *(const float4*)&qT[e*QST + s0 + 4*ty];
                float4 bb = *(const float4*)&qT[e*QST + k0 + 4*tx];
                acc[0][0]=fmaf(a.x,bb.x,acc[0][0]); acc[0][1]=fmaf(a.x,bb.y,acc[0][1]);
                acc[0][2]=fmaf(a.x,bb.z,acc[0][2]); acc[0][3]=fmaf(a.x,bb.w,acc[0][3]);
                acc[1][0]=fmaf(a.y,bb.x,acc[1][0]); acc[1][1]=fmaf(a.y,bb.y,acc[1][1]);
                acc[1][2]=fmaf(a.y,bb.z,acc[1][2]); acc[1][3]=fmaf(a.y,bb.w,acc[1][3]);
                acc[2][0]=fmaf(a.z,bb.x,acc[2][0]); acc[2][1]=fmaf(a.z,bb.y,acc[2][1]);
                acc[2][2]=fmaf(a.z,bb.z,acc[2][2]); acc[2][3]=fmaf(a.z,bb.w,acc[2][3]);
                acc[3][0]=fmaf(a.w,bb.x,acc[3][0]); acc[3][1]=fmaf(a.w,bb.y,acc[3][1]);
                acc[3][2]=fmaf(a.w,bb.z,acc[3][2]); acc[3][3]=fmaf(a.w,bb.w,acc[3][3]);
            }
#pragma unroll
            for (int i = 0; i < 4; i++)
                *(float4*)&sc[(4*ty+i)*SST + k0 + 4*tx] =
                    make_float4(acc[i][0], acc[i][1], acc[i][2], acc[i][3]);
        }
        __syncthreads();
        for (int rr = w; rr < 64; rr += 8) {
            int s = s0 + rr;
            if (maskS[s] == 0.f) {
                for (int c = l; c < 256; c += 32) sc[rr*SST + c] = 0.f;
            } else {
                float v[8]; float mx = FMIN2;
#pragma unroll
                for (int c = 0; c < 8; c++) {
                    float rawv = sc[rr*SST + l + 32*c] * 0.125f;
                    if (maskS[l + 32*c] == 0.f) rawv = NEGV;
                    v[c] = rawv; mx = fmaxf(mx, rawv);
                }
#pragma unroll
                for (int o = 16; o; o >>= 1) mx = fmaxf(mx, __shfl_xor_sync(~0u, mx, o));
                float sum = 0.f;
#pragma unroll
                for (int c = 0; c < 8; c++) { v[c] = expf(v[c] - mx); sum += v[c]; }
#pragma unroll
                for (int o = 16; o; o >>= 1) sum += __shfl_xor_sync(~0u, sum, o);
                float inv = 1.f / sum;
#pragma unroll
                for (int c = 0; c < 8; c++) sc[rr*SST + l + 32*c] = v[c]*inv;
            }
        }
        __syncthreads();
        {
            float acc[4][4];
#pragma unroll
            for (int i = 0; i < 4; i++)
#pragma unroll
                for (int j = 0; j < 4; j++) acc[i][j] = 0.f;
            const float* ar = sc + 4*ty*SST;
#pragma unroll 2
            for (int k = 0; k < 256; k++) {
                float4 bv = *(const float4*)&itemsS[k*IST + 4*tx];
                float a0 = ar[k], a1 = ar[SST+k], a2 = ar[2*SST+k], a3 = ar[3*SST+k];
                acc[0][0]=fmaf(a0,bv.x,acc[0][0]); acc[0][1]=fmaf(a0,bv.y,acc[0][1]);
                acc[0][2]=fmaf(a0,bv.z,acc[0][2]); acc[0][3]=fmaf(a0,bv.w,acc[0][3]);
                acc[1][0]=fmaf(a1,bv.x,acc[1][0]); acc[1][1]=fmaf(a1,bv.y,acc[1][1]);
                acc[1][2]=fmaf(a1,bv.z,acc[1][2]); acc[1][3]=fmaf(a1,bv.w,acc[1][3]);
                acc[2][0]=fmaf(a2,bv.x,acc[2][0]); acc[2][1]=fmaf(a2,bv.y,acc[2][1]);
                acc[2][2]=fmaf(a2,bv.z,acc[2][2]); acc[2][3]=fmaf(a2,bv.w,acc[2][3]);
                acc[3][0]=fmaf(a3,bv.x,acc[3][0]); acc[3][1]=fmaf(a3,bv.y,acc[3][1]);
                acc[3][2]=fmaf(a3,bv.z,acc[3][2]); acc[3][3]=fmaf(a3,bv.w,acc[3][3]);
            }
            float* so = &g_seq[((size_t)b*SS + s0 + 4*ty)*DD + 4*tx];
#pragma unroll
            for (int i = 0; i < 4; i++) {
                *(float4*)(so + (size_t)i*DD) =
                    make_float4(acc[i][0], acc[i][1], acc[i][2], acc[i][3]);
                rs0 += acc[i][0]; rs1 += acc[i][1]; rs2 += acc[i][2]; rs3 += acc[i][3];
            }
        }
        __syncthreads();
    }
    atomicAdd(&colS[4*tx],   rs0);
    atomicAdd(&colS[4*tx+1], rs1);
    atomicAdd(&colS[4*tx+2], rs2);
    atomicAdd(&colS[4*tx+3], rs3);
    __syncthreads();

    // ---- mean_h, logits, logits@trans, top-4 ----
    float* W1S = sc; float* logitsS = sc + 4096; float* mhS = sc + 4608;
    float* wrS = sc + 4672; float* aqS = sc + 5712; float* uebS = sc + 5968;
    for (int i = t; i < 4096; i += 256) W1S[i] = W1[i];
    __syncthreads();
    if (t < 64) meanS[t] = (colS[t] + g_posSum[t]) * sDen;
    __syncthreads();
    if (t < 64) {
        float a = 0.f;
#pragma unroll 16
        for (int e = 0; e < 64; e++) a = fmaf(meanS[e], W1S[e*64 + t], a);
        mhS[t] = tanhf(a);
    }
    __syncthreads();
    for (int c = t; c < 512; c += 256) {
        const float4* cr = (const float4*)&g_cand[c*64];
        float a = 0.f;
#pragma unroll
        for (int e4 = 0; e4 < 16; e4++) {
            float4 cv = cr[e4];
            a = fmaf(cv.x, mhS[4*e4], a);   a = fmaf(cv.y, mhS[4*e4+1], a);
            a = fmaf(cv.z, mhS[4*e4+2], a); a = fmaf(cv.w, mhS[4*e4+3], a);
        }
        logitsS[c] = a;
    }
    __syncthreads();
    float lg0, lg1;
    {
        const float4* tr = (const float4*)&g_transT[(size_t)t*CC];
        float a = 0.f;
#pragma unroll 8
        for (int i4 = 0; i4 < 128; i4++) {
            float4 tv = tr[i4];
            a = fmaf(tv.x, logitsS[4*i4], a);   a = fmaf(tv.y, logitsS[4*i4+1], a);
            a = fmaf(tv.z, logitsS[4*i4+2], a); a = fmaf(tv.w, logitsS[4*i4+3], a);
        }
        lg0 = a;
        tr = (const float4*)&g_transT[(size_t)(t+256)*CC];
        a = 0.f;
#pragma unroll 8
        for (int i4 = 0; i4 < 128; i4++) {
            float4 tv = tr[i4];
            a = fmaf(tv.x, logitsS[4*i4], a);   a = fmaf(tv.y, logitsS[4*i4+1], a);
            a = fmaf(tv.z, logitsS[4*i4+2], a); a = fmaf(tv.w, logitsS[4*i4+3], a);
        }
        lg1 = a;
    }
    __syncthreads();
    logitsS[t] = lg0; logitsS[t+256] = lg1;
    __syncthreads();
    for (int p = 0; p < 4; p++) {
        float bv = logitsS[t]; int bi = t;
        float v2 = logitsS[t+256];
        if (v2 > bv) { bv = v2; bi = t+256; }
#pragma unroll
        for (int o = 16; o; o >>= 1) {
            float ov = __shfl_xor_sync(~0u, bv, o);
            int   oi = __shfl_xor_sync(~0u, bi, o);
            if (ov > bv || (ov == bv && oi < bi)) { bv = ov; bi = oi; }
        }
        if (l == 0) { rv[w] = bv; riS[w] = bi; }
        __syncthreads();
        if (t == 0) {
            float B2 = rv[0]; int BI = riS[0];
            for (int i = 1; i < 8; i++)
                if (rv[i] > B2 || (rv[i] == B2 && riS[i] < BI)) { B2 = rv[i]; BI = riS[i]; }
            idxS[p] = BI; logitsS[BI] = FMIN2;
        }
        __syncthreads();
    }
    { int k = t >> 6, d = t & 63; aqS[t] = g_cand[(size_t)idxS[k]*64 + d]; }
    __syncthreads();

    // ---- D: multi-interest attention ----
    {
        float x[64];
        const float* sr = &g_seq[((size_t)b*SS + t)*DD];
#pragma unroll 16
        for (int e = 0; e < 64; e++) x[e] = sr[e] + pos[t*DD + e];
        float wv0 = 0.f, wv1 = 0.f, wv2 = 0.f, wv3 = 0.f;
        for (int d = 0; d < 64; d += 4) {
            float a0 = 0.f, a1 = 0.f, a2 = 0.f, a3 = 0.f;
#pragma unroll 16
            for (int e = 0; e < 64; e++) {
                float4 w4 = *(const float4*)&W1S[e*64 + d];
                float xe = x[e];
                a0 = fmaf(xe, w4.x, a0); a1 = fmaf(xe, w4.y, a1);
                a2 = fmaf(xe, w4.z, a2); a3 = fmaf(xe, w4.w, a3);
            }
            a0 = tanhf(a0); a1 = tanhf(a1); a2 = tanhf(a2); a3 = tanhf(a3);
            float4 q0 = *(const float4*)&aqS[0*64 + d];
            float4 q1 = *(const float4*)&aqS[1*64 + d];
            float4 q2 = *(const float4*)&aqS[2*64 + d];
            float4 q3 = *(const float4*)&aqS[3*64 + d];
            wv0 += fmaf(a0,q0.x, fmaf(a1,q0.y, fmaf(a2,q0.z, a3*q0.w)));
            wv1 += fmaf(a0,q1.x, fmaf(a1,q1.y, fmaf(a2,q1.z, a3*q1.w)));
            wv2 += fmaf(a0,q2.x, fmaf(a1,q2.y, fmaf(a2,q2.z, a3*q2.w)));
            wv3 += fmaf(a0,q3.x, fmaf(a1,q3.y, fmaf(a2,q3.z, a3*q3.w)));
        }
        float m = maskS[t];
        wrS[0*260 + t] = (m == 0.f) ? NEGV : wv0;
        wrS[1*260 + t] = (m == 0.f) ? NEGV : wv1;
        wrS[2*260 + t] = (m == 0.f) ? NEGV : wv2;
        wrS[3*260 + t] = (m == 0.f) ? NEGV : wv3;
    }
    __syncthreads();
    if (w < 4) {
        float v[8]; float mx = FMIN2;
#pragma unroll
        for (int c = 0; c < 8; c++) { v[c] = wrS[w*260 + l + 32*c]; mx = fmaxf(mx, v[c]); }
#pragma unroll
        for (int o = 16; o; o >>= 1) mx = fmaxf(mx, __shfl_xor_sync(~0u, mx, o));
        float sum = 0.f;
#pragma unroll
        for (int c = 0; c < 8; c++) { v[c] = expf(v[c] - mx); sum += v[c]; }
#pragma unroll
        for (int o = 16; o; o >>= 1) sum += __shfl_xor_sync(~0u, sum, o);
        float inv = 1.f / sum;
#pragma unroll
        for (int c = 0; c < 8; c++) wrS[w*260 + l + 32*c] = v[c]*inv;
    }
    __syncthreads();
    {
        int k = t >> 6, d = t & 63;
        const float* wp = &wrS[k*260];
        const float* sp = &g_seq[(size_t)b*SS*DD + d];
        float a = 0.f;
#pragma unroll 8
        for (int s = 0; s < 256; s++) a = fmaf(wp[s], sp[(size_t)s*64], a);
        uebS[t] = a;
        long off = 32768 + (long)b*256 + t;
        if (off < out_size) out[off] = a;
    }
    __syncthreads();
    if (w < 4) {
        float p = uebS[w*64 + l]*itemS[l] + uebS[w*64 + l + 32]*itemS[l + 32];
#pragma unroll
        for (int o = 16; o; o >>= 1) p += __shfl_xor_sync(~0u, p, o);
        if (l == 0) dotS[w] = p;
    }
    __syncthreads();
    if (t == 0) {
        float bv2 = dotS[0]; int bi2 = 0;
        for (int k = 1; k < 4; k++) if (dotS[k] > bv2) { bv2 = dotS[k]; bi2 = k; }
        ridxS = bi2;
    }
    __syncthreads();
    if (t < 64) {
        long off = (long)b*64 + t;
        if (off < out_size) out[off] = uebS[ridxS*64 + t];
    }
    if (t < 4) {
        long off = 163840 + (long)b*4 + t;
        if (off < out_size) out[off] = (float)idxS[t];
    }
}

extern "C" void kernel_launch(void* const* d_in, const int* in_sizes, int n_in,
                              void* d_out, int out_size) {
    const float* E    = (const float*)d_in[0];
    const float* W1   = (const float*)d_in[1];
    const float* W2   = (const float*)d_in[2];
    const float* W3   = (const float*)d_in[3];
    const float* W4   = (const float*)d_in[4];
    const float* pos  = (const float*)d_in[5];
    const float* dw   = (const float*)d_in[6];
    const float* db   = (const float*)d_in[7];
    const int*   his  = (const int*)d_in[8];
    const int*   mask = (const int*)d_in[9];
    const int*   midb = (const int*)d_in[10];
    float* out = (float*)d_out;

    cudaFuncSetAttribute(k_att, cudaFuncAttributeMaxDynamicSharedMemorySize,
                         SM_FLOATS * (int)sizeof(float));

    k_pre<<<1, 256>>>(pos);
    k_wmean<<<1184, 256>>>(E, W2);
    k_cand<<<CC, DD>>>(W3, W1, W4);
    k_trans<<<CC, 256>>>();
    k_att<<<BB, 256, SM_FLOATS * sizeof(float)>>>(E, W1, pos, dw, db,
                                                  his, mask, midb,
                                                  out, (long)out_size);
}

// round 9
// speedup vs baseline: 1.0684x; 1.0680x over previous
#include <cuda_runtime.h>
#include <math.h>

#define NMID 500000
#define DD 64
#define KI 4
#define CC 512
#define SS 256
#define BB 512
#define NEGV (-4294967295.0f)
#define FMIN2 (-3.402823466e38f)

#define IST 68
#define QST 264
#define SST 260
#define SM_FLOATS 51328

typedef unsigned long long u64;

__device__ __forceinline__ u64 splat2(float x) {
    u64 r; asm("mov.b64 %0, {%1,%1};" : "=l"(r) : "f"(x)); return r;
}
__device__ __forceinline__ void ffma2(u64& acc, u64 a, u64 b) {
    asm("fma.rn.f32x2 %0, %1, %2, %0;" : "+l"(acc) : "l"(a), "l"(b));
}
__device__ __forceinline__ float2 unpack2(u64 v) {
    float2 f; asm("mov.b64 {%0,%1}, %2;" : "=f"(f.x), "=f"(f.y) : "l"(v)); return f;
}
__device__ __forceinline__ float tanh_fast(float x) {
    float t = __expf(2.f * x);
    return 1.f - __fdividef(2.f, t + 1.f);
}

__device__ float g_wmean[KI*DD];
__device__ float g_posSum[DD];
__device__ float g_cand0[CC*DD];
__device__ float g_cand[CC*DD];
__device__ float g_candW4[CC*DD];
__device__ float g_transT[(size_t)CC*CC];
__device__ float g_seq[(size_t)BB*SS*DD];

// ---------------- K0 ----------------
__global__ void k_pre(const float* __restrict__ pos) {
    int t = threadIdx.x;
    if (t < KI*DD) g_wmean[t] = 0.f;
    if (t < DD) {
        float s = 0.f;
        for (int i = 0; i < SS; i++) s += pos[i*DD + t];
        g_posSum[t] = s;
    }
}

// ---------------- K1 ----------------
__global__ void k_wmean(const float* __restrict__ E, const float* __restrict__ W2) {
    __shared__ float red[8*256];
    int t = threadIdx.x, l = t & 31, wi = t >> 5;
    int gw = (blockIdx.x*blockDim.x + t) >> 5;
    int TW = (gridDim.x*blockDim.x) >> 5;
    float2 w2[KI];
#pragma unroll
    for (int k = 0; k < KI; k++) {
        w2[k].x = W2[k*DD + 2*l];
        w2[k].y = W2[k*DD + 2*l + 1];
    }
    float2 acc[KI];
#pragma unroll
    for (int k = 0; k < KI; k++) acc[k] = make_float2(0.f, 0.f);
    const float2* E2 = (const float2*)E;
    for (long n = gw; n < NMID; n += TW) {
        float2 e = E2[n*32 + l];
#pragma unroll
        for (int k = 0; k < KI; k++) {
            float p = fmaf(e.x, w2[k].x, e.y*w2[k].y);
#pragma unroll
            for (int o = 16; o; o >>= 1) p += __shfl_xor_sync(~0u, p, o);
            acc[k].x = fmaf(p, e.x, acc[k].x);
            acc[k].y = fmaf(p, e.y, acc[k].y);
        }
    }
#pragma unroll
    for (int k = 0; k < KI; k++) {
        red[wi*256 + k*64 + 2*l]     = acc[k].x;
        red[wi*256 + k*64 + 2*l + 1] = acc[k].y;
    }
    __syncthreads();
    if (t < 256) {
        float s = 0.f;
#pragma unroll
        for (int w = 0; w < 8; w++) s += red[w*256 + t];
        atomicAdd(&g_wmean[t], s);
    }
}

// ---------------- K2 ----------------
__global__ void k_cand(const float* __restrict__ W3, const float* __restrict__ W1,
                       const float* __restrict__ W4) {
    __shared__ float row[DD];
    int d = threadIdx.x, c = blockIdx.x;
    float v = 0.f;
#pragma unroll
    for (int k = 0; k < KI; k++) v = fmaf(W3[k*CC + c], g_wmean[k*DD + d], v);
    row[d] = v;
    g_cand0[c*DD + d] = v;
    __syncthreads();
    float a = 0.f, bv = 0.f;
#pragma unroll 8
    for (int e = 0; e < DD; e++) {
        float r = row[e];
        a  = fmaf(r, W1[e*DD + d], a);
        bv = fmaf(r, W4[e*DD + d], bv);
    }
    g_cand[c*DD + d]   = tanhf(a);
    g_candW4[c*DD + d] = bv;
}

// ---------------- K3: exact round-7 arithmetic (expf, scalar float4 dots) ----------------
__global__ void k_trans() {
    __shared__ float c0j[DD];
    __shared__ float red[8];
    __shared__ float bmax, bsum;
    int t = threadIdx.x, j = blockIdx.x, w = t >> 5, l = t & 31;
    if (t < DD) c0j[t] = g_cand0[j*DD + t];
    __syncthreads();
    float v0 = 0.f, v1 = 0.f;
    {
        const float4* r4 = (const float4*)(g_candW4 + (size_t)t*DD);
#pragma unroll
        for (int e4 = 0; e4 < 16; e4++) {
            float4 q = r4[e4];
            v0 = fmaf(q.x, c0j[4*e4], v0);   v0 = fmaf(q.y, c0j[4*e4+1], v0);
            v0 = fmaf(q.z, c0j[4*e4+2], v0); v0 = fmaf(q.w, c0j[4*e4+3], v0);
        }
        r4 = (const float4*)(g_candW4 + (size_t)(t+256)*DD);
#pragma unroll
        for (int e4 = 0; e4 < 16; e4++) {
            float4 q = r4[e4];
            v1 = fmaf(q.x, c0j[4*e4], v1);   v1 = fmaf(q.y, c0j[4*e4+1], v1);
            v1 = fmaf(q.z, c0j[4*e4+2], v1); v1 = fmaf(q.w, c0j[4*e4+3], v1);
        }
    }
    float m = fmaxf(v0, v1);
#pragma unroll
    for (int o = 16; o; o >>= 1) m = fmaxf(m, __shfl_xor_sync(~0u, m, o));
    if (l == 0) red[w] = m;
    __syncthreads();
    if (t == 0) { float mm = red[0]; for (int i = 1; i < 8; i++) mm = fmaxf(mm, red[i]); bmax = mm; }
    __syncthreads();
    float p0 = expf(v0 - bmax), p1 = expf(v1 - bmax);
    float s = p0 + p1;
#pragma unroll
    for (int o = 16; o; o >>= 1) s += __shfl_xor_sync(~0u, s, o);
    if (l == 0) red[w] = s;
    __syncthreads();
    if (t == 0) { float ss = 0.f; for (int i = 0; i < 8; i++) ss += red[i]; bsum = ss; }
    __syncthreads();
    float inv = 1.f / bsum;
    g_transT[(size_t)j*CC + t]       = p0 * inv;
    g_transT[(size_t)j*CC + t + 256] = p1 * inv;
}

// ---------------- K4 ----------------
__global__ void __launch_bounds__(512,1) k_att(
    const float* __restrict__ E, const float* __restrict__ W1,
    const float* __restrict__ pos, const float* __restrict__ dw,
    const float* __restrict__ db, const int* __restrict__ his,
    const int* __restrict__ mask, const int* __restrict__ midb,
    float* __restrict__ out, long out_size)
{
    extern __shared__ float sm[];
    float* itemsS = sm;
    float* qT     = sm + 17408;
    float* sc     = sm + 34304;
    float* maskS  = sm + 50944;
    float* colS   = sm + 51200;
    float* meanS  = sm + 51264;
    __shared__ float sDen;
    __shared__ float rv[16]; __shared__ int riS[16];
    __shared__ int idxS[4]; __shared__ float itemS[64];
    __shared__ float dotS[4]; __shared__ int ridxS;

    int b = blockIdx.x, t = threadIdx.x, w = t >> 5, l = t & 31;

    // ---- A: loads ----
    if (t < SS) maskS[t] = (float)mask[b*SS + t];
    if (t < 64) colS[t] = 0.f;
    {
        float* dwS = sc; float* biasS = sc + 4096;
        for (int i = t; i < 4096; i += 512) dwS[i] = dw[i];
        if (t < 64) biasS[t] = db[t];
        if (t < 64) itemS[t] = E[(size_t)midb[b]*DD + t];
    }
    {
        const float4* E4 = (const float4*)E;
        float4* it4 = (float4*)itemsS;
        const int* hr = his + b*SS;
        for (int f = t; f < SS*16; f += 512) {
            int s = f >> 4, c = f & 15;
            it4[s*17 + c] = E4[(size_t)hr[s]*16 + c];
        }
    }
    __syncthreads();
    if (w == 0) {
        float s = 0.f;
        for (int i = l; i < SS; i += 32) s += maskS[i];
#pragma unroll
        for (int o = 16; o; o >>= 1) s += __shfl_xor_sync(~0u, s, o);
        if (l == 0) sDen = 1.f / (s + 1e-9f);
    }

    // ---- B: qT = tanh((items+pos)@dense_w + b); f32x2 accum (bitwise = scalar), tanhf ----
    {
        float* dwS = sc; float* biasS = sc + 4096;
        int s = t >> 1, half = t & 1;
        int d0 = 32*half;
        u64 acc[16];
#pragma unroll
        for (int i = 0; i < 16; i++) acc[i] = 0ull;
#pragma unroll 4
        for (int e = 0; e < 64; e++) {
            float xe = itemsS[s*IST + e] + pos[s*DD + e];
            u64 xs = splat2(xe);
            const ulonglong2* wp = (const ulonglong2*)&dwS[e*64 + d0];
#pragma unroll
            for (int q = 0; q < 8; q++) {
                ulonglong2 wv = wp[q];
                ffma2(acc[2*q],   xs, wv.x);
                ffma2(acc[2*q+1], xs, wv.y);
            }
        }
#pragma unroll
        for (int i = 0; i < 16; i++) {
            float2 p = unpack2(acc[i]);
            int d = d0 + 2*i;
            qT[d*QST + s]     = tanhf(p.x + biasS[d]);
            qT[(d+1)*QST + s] = tanhf(p.y + biasS[d+1]);
        }
    }
    __syncthreads();

    // ---- C ----
    float rs0 = 0.f, rs1 = 0.f, rs2 = 0.f, rs3 = 0.f;
    for (int g = 0; g < 4; g++) {
        int s0 = g*64;
        {
            int ty = t >> 6;
            int tx = t & 63;
            u64 acc[4][4];
#pragma unroll
            for (int i = 0; i < 4; i++)
#pragma unroll
                for (int j = 0; j < 4; j++) acc[i][j] = 0ull;
#pragma unroll 4
            for (int e = 0; e < 64; e++) {
                const float* qe = &qT[e*QST];
                ulonglong2 a01 = *(const ulonglong2*)&qe[s0 + 8*ty];
                ulonglong2 a23 = *(const ulonglong2*)&qe[s0 + 8*ty + 4];
                float4 bf = *(const float4*)&qe[4*tx];
                u64 b0 = splat2(bf.x), b1 = splat2(bf.y), b2 = splat2(bf.z), b3 = splat2(bf.w);
                ffma2(acc[0][0], a01.x, b0); ffma2(acc[0][1], a01.x, b1);
                ffma2(acc[0][2], a01.x, b2); ffma2(acc[0][3], a01.x, b3);
                ffma2(acc[1][0], a01.y, b0); ffma2(acc[1][1], a01.y, b1);
                ffma2(acc[1][2], a01.y, b2); ffma2(acc[1][3], a01.y, b3);
                ffma2(acc[2][0], a23.x, b0); ffma2(acc[2][1], a23.x, b1);
                ffma2(acc[2][2], a23.x, b2); ffma2(acc[2][3], a23.x, b3);
                ffma2(acc[3][0], a23.y, b0); ffma2(acc[3][1], a23.y, b1);
                ffma2(acc[3][2], a23.y, b2); ffma2(acc[3][3], a23.y, b3);
            }
#pragma unroll
            for (int rp = 0; rp < 4; rp++) {
                float2 c0 = unpack2(acc[rp][0]), c1 = unpack2(acc[rp][1]);
                float2 c2 = unpack2(acc[rp][2]), c3 = unpack2(acc[rp][3]);
                *(float4*)&sc[(8*ty + 2*rp)*SST + 4*tx] =
                    make_float4(c0.x, c1.x, c2.x, c3.x);
                *(float4*)&sc[(8*ty + 2*rp + 1)*SST + 4*tx] =
                    make_float4(c0.y, c1.y, c2.y, c3.y);
            }
        }
        __syncthreads();
        // C2: masked row softmax — accurate expf (feeds seq -> mean -> logits -> idx)
        for (int rr = w; rr < 64; rr += 16) {
            int s = s0 + rr;
            if (maskS[s] == 0.f) {
                for (int c = l; c < 256; c += 32) sc[rr*SST + c] = 0.f;
            } else {
                float v[8]; float mx = FMIN2;
#pragma unroll
                for (int c = 0; c < 8; c++) {
                    float rawv = sc[rr*SST + l + 32*c] * 0.125f;
                    if (maskS[l + 32*c] == 0.f) rawv = NEGV;
                    v[c] = rawv; mx = fmaxf(mx, rawv);
                }
#pragma unroll
                for (int o = 16; o; o >>= 1) mx = fmaxf(mx, __shfl_xor_sync(~0u, mx, o));
                float sum = 0.f;
#pragma unroll
                for (int c = 0; c < 8; c++) { v[c] = expf(v[c] - mx); sum += v[c]; }
#pragma unroll
                for (int o = 16; o; o >>= 1) sum += __shfl_xor_sync(~0u, sum, o);
                float inv = 1.f / sum;
#pragma unroll
                for (int c = 0; c < 8; c++) sc[rr*SST + l + 32*c] = v[c]*inv;
            }
        }
        __syncthreads();
        {
            int ry = t >> 4;
            int rx = t & 15;
            u64 a00 = 0ull, a01v = 0ull, a10 = 0ull, a11 = 0ull;
            const float* r0p = &sc[(2*ry)*SST];
            const float* r1p = &sc[(2*ry + 1)*SST];
#pragma unroll 2
            for (int k = 0; k < 256; k += 2) {
                float2 af0 = *(const float2*)&r0p[k];
                float2 af1 = *(const float2*)&r1p[k];
                ulonglong2 bk  = *(const ulonglong2*)&itemsS[k*IST + 4*rx];
                ulonglong2 bk1 = *(const ulonglong2*)&itemsS[(k+1)*IST + 4*rx];
                u64 s00 = splat2(af0.x), s01 = splat2(af0.y);
                u64 s10 = splat2(af1.x), s11 = splat2(af1.y);
                ffma2(a00,  s00, bk.x);  ffma2(a01v, s00, bk.y);
                ffma2(a10,  s10, bk.x);  ffma2(a11,  s10, bk.y);
                ffma2(a00,  s01, bk1.x); ffma2(a01v, s01, bk1.y);
                ffma2(a10,  s11, bk1.x); ffma2(a11,  s11, bk1.y);
            }
            float2 u00 = unpack2(a00), u01 = unpack2(a01v);
            float2 u10 = unpack2(a10), u11 = unpack2(a11);
            float4 row0 = make_float4(u00.x, u00.y, u01.x, u01.y);
            float4 row1 = make_float4(u10.x, u10.y, u11.x, u11.y);
            float* so = &g_seq[((size_t)b*SS + s0 + 2*ry)*DD + 4*rx];
            *(float4*)so = row0;
            *(float4*)(so + DD) = row1;
            rs0 += row0.x + row1.x; rs1 += row0.y + row1.y;
            rs2 += row0.z + row1.z; rs3 += row0.w + row1.w;
        }
        __syncthreads();
    }
    {
        int rx = t & 15;
        atomicAdd(&colS[4*rx],   rs0);
        atomicAdd(&colS[4*rx+1], rs1);
        atomicAdd(&colS[4*rx+2], rs2);
        atomicAdd(&colS[4*rx+3], rs3);
    }
    // ---- mean_h, logits, logits@trans, top-4 (accurate path: tanhf, scalar fp32) ----
    float* W1S = sc; float* logitsS = sc + 4096; float* mhS = sc + 4608;
    float* wrS = sc + 4672; float* aqS = sc + 5712; float* uebS = sc + 5968;
    for (int i = t; i < 4096; i += 512) W1S[i] = W1[i];
    __syncthreads();
    if (t < 64) meanS[t] = (colS[t] + g_posSum[t]) * sDen;
    __syncthreads();
    if (t < 64) {
        float a = 0.f;
#pragma unroll 16
        for (int e = 0; e < 64; e++) a = fmaf(meanS[e], W1S[e*64 + t], a);
        mhS[t] = tanhf(a);
    }
    __syncthreads();
    {
        const float4* cr = (const float4*)&g_cand[(size_t)t*64];
        float a = 0.f;
#pragma unroll
        for (int e4 = 0; e4 < 16; e4++) {
            float4 cv = cr[e4];
            a = fmaf(cv.x, mhS[4*e4], a);   a = fmaf(cv.y, mhS[4*e4+1], a);
            a = fmaf(cv.z, mhS[4*e4+2], a); a = fmaf(cv.w, mhS[4*e4+3], a);
        }
        logitsS[t] = a;
    }
    __syncthreads();
    float lgv;
    {
        const float4* tr = (const float4*)&g_transT[(size_t)t*CC];
        float a = 0.f;
#pragma unroll 8
        for (int i4 = 0; i4 < 128; i4++) {
            float4 tv = tr[i4];
            a = fmaf(tv.x, logitsS[4*i4], a);   a = fmaf(tv.y, logitsS[4*i4+1], a);
            a = fmaf(tv.z, logitsS[4*i4+2], a); a = fmaf(tv.w, logitsS[4*i4+3], a);
        }
        lgv = a;
    }
    __syncthreads();
    logitsS[t] = lgv;
    __syncthreads();
    for (int p = 0; p < 4; p++) {
        float bv = logitsS[t]; int bi = t;
#pragma unroll
        for (int o = 16; o; o >>= 1) {
            float ov = __shfl_xor_sync(~0u, bv, o);
            int   oi = __shfl_xor_sync(~0u, bi, o);
            if (ov > bv || (ov == bv && oi < bi)) { bv = ov; bi = oi; }
        }
        if (l == 0) { rv[w] = bv; riS[w] = bi; }
        __syncthreads();
        if (t == 0) {
            float B2 = rv[0]; int BI = riS[0];
            for (int i = 1; i < 16; i++)
                if (rv[i] > B2 || (rv[i] == B2 && riS[i] < BI)) { B2 = rv[i]; BI = riS[i]; }
            idxS[p] = BI; logitsS[BI] = FMIN2;
        }
        __syncthreads();
    }
    if (t < 256) { int k = t >> 6, d = t & 63; aqS[t] = g_cand[(size_t)idxS[k]*64 + d]; }
    __syncthreads();

    // ---- D: multi-interest attention (fast math OK: feeds outputs 0/1 only) ----
    {
        int s = t >> 1, half = t & 1;
        int d0 = 32*half;
        u64 acc[16];
#pragma unroll
        for (int i = 0; i < 16; i++) acc[i] = 0ull;
        const float* sr = &g_seq[((size_t)b*SS + s)*DD];
#pragma unroll 4
        for (int e = 0; e < 64; e++) {
            float xe = sr[e] + pos[s*DD + e];
            u64 xs = splat2(xe);
            const ulonglong2* wp = (const ulonglong2*)&W1S[e*64 + d0];
#pragma unroll
            for (int q = 0; q < 8; q++) {
                ulonglong2 wv = wp[q];
                ffma2(acc[2*q],   xs, wv.x);
                ffma2(acc[2*q+1], xs, wv.y);
            }
        }
        float ihv[32];
#pragma unroll
        for (int i = 0; i < 16; i++) {
            float2 p = unpack2(acc[i]);
            ihv[2*i]   = tanh_fast(p.x);
            ihv[2*i+1] = tanh_fast(p.y);
        }
        float wv[4];
#pragma unroll
        for (int k = 0; k < 4; k++) {
            float a = 0.f;
            const float* aq = &aqS[k*64 + d0];
#pragma unroll
            for (int i = 0; i < 32; i++) a = fmaf(ihv[i], aq[i], a);
            a += __shfl_xor_sync(~0u, a, 1);
            wv[k] = a;
        }
        if (half == 0) {
            float m = maskS[s];
#pragma unroll
            for (int k = 0; k < 4; k++)
                wrS[k*260 + s] = (m == 0.f) ? NEGV : wv[k];
        }
    }
    __syncthreads();
    if (w < 4) {
        float v[8]; float mx = FMIN2;
#pragma unroll
        for (int c = 0; c < 8; c++) { v[c] = wrS[w*260 + l + 32*c]; mx = fmaxf(mx, v[c]); }
#pragma unroll
        for (int o = 16; o; o >>= 1) mx = fmaxf(mx, __shfl_xor_sync(~0u, mx, o));
        float sum = 0.f;
#pragma unroll
        for (int c = 0; c < 8; c++) { v[c] = __expf(v[c] - mx); sum += v[c]; }
#pragma unroll
        for (int o = 16; o; o >>= 1) sum += __shfl_xor_sync(~0u, sum, o);
        float inv = 1.f / sum;
#pragma unroll
        for (int c = 0; c < 8; c++) wrS[w*260 + l + 32*c] = v[c]*inv;
    }
    __syncthreads();
    if (t < 256) {
        int k = t >> 6, d = t & 63;
        const float* wp = &wrS[k*260];
        const float* sp = &g_seq[(size_t)b*SS*DD + d];
        float a = 0.f;
#pragma unroll 8
        for (int s = 0; s < 256; s++) a = fmaf(wp[s], sp[(size_t)s*64], a);
        uebS[t] = a;
        long off = 32768 + (long)b*256 + t;
        if (off < out_size) out[off] = a;
    }
    __syncthreads();
    if (w < 4) {
        float p = uebS[w*64 + l]*itemS[l] + uebS[w*64 + l + 32]*itemS[l + 32];
#pragma unroll
        for (int o = 16; o; o >>= 1) p += __shfl_xor_sync(~0u, p, o);
        if (l == 0) dotS[w] = p;
    }
    __syncthreads();
    if (t == 0) {
        float bv2 = dotS[0]; int bi2 = 0;
        for (int k = 1; k < 4; k++) if (dotS[k] > bv2) { bv2 = dotS[k]; bi2 = k; }
        ridxS = bi2;
    }
    __syncthreads();
    if (t < 64) {
        long off = (long)b*64 + t;
        if (off < out_size) out[off] = uebS[ridxS*64 + t];
    }
    if (t < 4) {
        long off = 163840 + (long)b*4 + t;
        if (off < out_size) out[off] = (float)idxS[t];
    }
}

extern "C" void kernel_launch(void* const* d_in, const int* in_sizes, int n_in,
                              void* d_out, int out_size) {
    const float* E    = (const float*)d_in[0];
    const float* W1   = (const float*)d_in[1];
    const float* W2   = (const float*)d_in[2];
    const float* W3   = (const float*)d_in[3];
    const float* W4   = (const float*)d_in[4];
    const float* pos  = (const float*)d_in[5];
    const float* dw   = (const float*)d_in[6];
    const float* db   = (const float*)d_in[7];
    const int*   his  = (const int*)d_in[8];
    const int*   mask = (const int*)d_in[9];
    const int*   midb = (const int*)d_in[10];
    float* out = (float*)d_out;

    cudaFuncSetAttribute(k_att, cudaFuncAttributeMaxDynamicSharedMemorySize,
                         SM_FLOATS * (int)sizeof(float));

    k_pre<<<1, 256>>>(pos);
    k_wmean<<<1184, 256>>>(E, W2);
    k_cand<<<CC, DD>>>(W3, W1, W4);
    k_trans<<<CC, 256>>>();
    k_att<<<BB, 512, SM_FLOATS * sizeof(float)>>>(E, W1, pos, dw, db,
                                                  his, mask, midb,
                                                  out, (long)out_size);
}

// round 10
// speedup vs baseline: 1.0696x; 1.0011x over previous
#include <cuda_runtime.h>
#include <math.h>

#define NMID 500000
#define DD 64
#define KI 4
#define CC 512
#define SS 256
#define BB 512
#define NEGV (-4294967295.0f)
#define FMIN2 (-3.402823466e38f)

#define IST 68
#define QST 264
#define SST 260
#define SM_FLOATS 51328

typedef unsigned long long u64;

__device__ __forceinline__ u64 splat2(float x) {
    u64 r; asm("mov.b64 %0, {%1,%1};" : "=l"(r) : "f"(x)); return r;
}
__device__ __forceinline__ void ffma2(u64& acc, u64 a, u64 b) {
    asm("fma.rn.f32x2 %0, %1, %2, %0;" : "+l"(acc) : "l"(a), "l"(b));
}
__device__ __forceinline__ float2 unpack2(u64 v) {
    float2 f; asm("mov.b64 {%0,%1}, %2;" : "=f"(f.x), "=f"(f.y) : "l"(v)); return f;
}
__device__ __forceinline__ float tanh_fast(float x) {
    float t = __expf(2.f * x);
    return 1.f - __fdividef(2.f, t + 1.f);
}

__device__ float g_wmean[KI*DD];
__device__ float g_posSum[DD];
__device__ float g_cand0[CC*DD];
__device__ float g_cand[CC*DD];
__device__ float g_candW4[CC*DD];
__device__ float g_transT[(size_t)CC*CC];
__device__ float g_seq[(size_t)BB*SS*DD];

// ---------------- K0 ----------------
__global__ void k_pre(const float* __restrict__ pos) {
    int t = threadIdx.x;
    if (t < KI*DD) g_wmean[t] = 0.f;
    if (t < DD) {
        float s = 0.f;
        for (int i = 0; i < SS; i++) s += pos[i*DD + t];
        g_posSum[t] = s;
    }
}

// ---------------- K1 ----------------
__global__ void k_wmean(const float* __restrict__ E, const float* __restrict__ W2) {
    __shared__ float red[8*256];
    int t = threadIdx.x, l = t & 31, wi = t >> 5;
    int gw = (blockIdx.x*blockDim.x + t) >> 5;
    int TW = (gridDim.x*blockDim.x) >> 5;
    float2 w2[KI];
#pragma unroll
    for (int k = 0; k < KI; k++) {
        w2[k].x = W2[k*DD + 2*l];
        w2[k].y = W2[k*DD + 2*l + 1];
    }
    float2 acc[KI];
#pragma unroll
    for (int k = 0; k < KI; k++) acc[k] = make_float2(0.f, 0.f);
    const float2* E2 = (const float2*)E;
    for (long n = gw; n < NMID; n += TW) {
        float2 e = E2[n*32 + l];
#pragma unroll
        for (int k = 0; k < KI; k++) {
            float p = fmaf(e.x, w2[k].x, e.y*w2[k].y);
#pragma unroll
            for (int o = 16; o; o >>= 1) p += __shfl_xor_sync(~0u, p, o);
            acc[k].x = fmaf(p, e.x, acc[k].x);
            acc[k].y = fmaf(p, e.y, acc[k].y);
        }
    }
#pragma unroll
    for (int k = 0; k < KI; k++) {
        red[wi*256 + k*64 + 2*l]     = acc[k].x;
        red[wi*256 + k*64 + 2*l + 1] = acc[k].y;
    }
    __syncthreads();
    if (t < 256) {
        float s = 0.f;
#pragma unroll
        for (int w = 0; w < 8; w++) s += red[w*256 + t];
        atomicAdd(&g_wmean[t], s);
    }
}

// ---------------- K2 ----------------
__global__ void k_cand(const float* __restrict__ W3, const float* __restrict__ W1,
                       const float* __restrict__ W4) {
    __shared__ float row[DD];
    int d = threadIdx.x, c = blockIdx.x;
    float v = 0.f;
#pragma unroll
    for (int k = 0; k < KI; k++) v = fmaf(W3[k*CC + c], g_wmean[k*DD + d], v);
    row[d] = v;
    g_cand0[c*DD + d] = v;
    __syncthreads();
    float a = 0.f, bv = 0.f;
#pragma unroll 8
    for (int e = 0; e < DD; e++) {
        float r = row[e];
        a  = fmaf(r, W1[e*DD + d], a);
        bv = fmaf(r, W4[e*DD + d], bv);
    }
    g_cand[c*DD + d]   = tanhf(a);
    g_candW4[c*DD + d] = bv;
}

// ---------------- K3: exact round-7 arithmetic (expf, scalar float4 dots) ----------------
__global__ void k_trans() {
    __shared__ float c0j[DD];
    __shared__ float red[8];
    __shared__ float bmax, bsum;
    int t = threadIdx.x, j = blockIdx.x, w = t >> 5, l = t & 31;
    if (t < DD) c0j[t] = g_cand0[j*DD + t];
    __syncthreads();
    float v0 = 0.f, v1 = 0.f;
    {
        const float4* r4 = (const float4*)(g_candW4 + (size_t)t*DD);
#pragma unroll
        for (int e4 = 0; e4 < 16; e4++) {
            float4 q = r4[e4];
            v0 = fmaf(q.x, c0j[4*e4], v0);   v0 = fmaf(q.y, c0j[4*e4+1], v0);
            v0 = fmaf(q.z, c0j[4*e4+2], v0); v0 = fmaf(q.w, c0j[4*e4+3], v0);
        }
        r4 = (const float4*)(g_candW4 + (size_t)(t+256)*DD);
#pragma unroll
        for (int e4 = 0; e4 < 16; e4++) {
            float4 q = r4[e4];
            v1 = fmaf(q.x, c0j[4*e4], v1);   v1 = fmaf(q.y, c0j[4*e4+1], v1);
            v1 = fmaf(q.z, c0j[4*e4+2], v1); v1 = fmaf(q.w, c0j[4*e4+3], v1);
        }
    }
    float m = fmaxf(v0, v1);
#pragma unroll
    for (int o = 16; o; o >>= 1) m = fmaxf(m, __shfl_xor_sync(~0u, m, o));
    if (l == 0) red[w] = m;
    __syncthreads();
    if (t == 0) { float mm = red[0]; for (int i = 1; i < 8; i++) mm = fmaxf(mm, red[i]); bmax = mm; }
    __syncthreads();
    float p0 = expf(v0 - bmax), p1 = expf(v1 - bmax);
    float s = p0 + p1;
#pragma unroll
    for (int o = 16; o; o >>= 1) s += __shfl_xor_sync(~0u, s, o);
    if (l == 0) red[w] = s;
    __syncthreads();
    if (t == 0) { float ss = 0.f; for (int i = 0; i < 8; i++) ss += red[i]; bsum = ss; }
    __syncthreads();
    float inv = 1.f / bsum;
    g_transT[(size_t)j*CC + t]       = p0 * inv;
    g_transT[(size_t)j*CC + t + 256] = p1 * inv;
}

// ---------------- K4 ----------------
__global__ void __launch_bounds__(512,1) k_att(
    const float* __restrict__ E, const float* __restrict__ W1,
    const float* __restrict__ pos, const float* __restrict__ dw,
    const float* __restrict__ db, const int* __restrict__ his,
    const int* __restrict__ mask, const int* __restrict__ midb,
    float* __restrict__ out, long out_size)
{
    extern __shared__ float sm[];
    float* itemsS = sm;
    float* qT     = sm + 17408;
    float* sc     = sm + 34304;
    float* maskS  = sm + 50944;
    float* colS   = sm + 51200;
    float* meanS  = sm + 51264;
    __shared__ float sDen;
    __shared__ float rv[16]; __shared__ int riS[16];
    __shared__ int idxS[4]; __shared__ float itemS[64];
    __shared__ float dotS[4]; __shared__ int ridxS;

    int b = blockIdx.x, t = threadIdx.x, w = t >> 5, l = t & 31;

    // ---- A: loads ----
    if (t < SS) maskS[t] = (float)mask[b*SS + t];
    if (t < 64) colS[t] = 0.f;
    {
        float* dwS = sc; float* biasS = sc + 4096;
        for (int i = t; i < 4096; i += 512) dwS[i] = dw[i];
        if (t < 64) biasS[t] = db[t];
        if (t < 64) itemS[t] = E[(size_t)midb[b]*DD + t];
    }
    {
        const float4* E4 = (const float4*)E;
        float4* it4 = (float4*)itemsS;
        const int* hr = his + b*SS;
        for (int f = t; f < SS*16; f += 512) {
            int s = f >> 4, c = f & 15;
            it4[s*17 + c] = E4[(size_t)hr[s]*16 + c];
        }
    }
    __syncthreads();
    if (w == 0) {
        float s = 0.f;
        for (int i = l; i < SS; i += 32) s += maskS[i];
#pragma unroll
        for (int o = 16; o; o >>= 1) s += __shfl_xor_sync(~0u, s, o);
        if (l == 0) sDen = 1.f / (s + 1e-9f);
    }

    // ---- B: qT = tanh((items+pos)@dense_w + b); f32x2 accum (bitwise = scalar), tanhf ----
    {
        float* dwS = sc; float* biasS = sc + 4096;
        int s = t >> 1, half = t & 1;
        int d0 = 32*half;
        u64 acc[16];
#pragma unroll
        for (int i = 0; i < 16; i++) acc[i] = 0ull;
#pragma unroll 4
        for (int e = 0; e < 64; e++) {
            float xe = itemsS[s*IST + e] + pos[s*DD + e];
            u64 xs = splat2(xe);
            const ulonglong2* wp = (const ulonglong2*)&dwS[e*64 + d0];
#pragma unroll
            for (int q = 0; q < 8; q++) {
                ulonglong2 wv = wp[q];
                ffma2(acc[2*q],   xs, wv.x);
                ffma2(acc[2*q+1], xs, wv.y);
            }
        }
#pragma unroll
        for (int i = 0; i < 16; i++) {
            float2 p = unpack2(acc[i]);
            int d = d0 + 2*i;
            qT[d*QST + s]     = tanhf(p.x + biasS[d]);
            qT[(d+1)*QST + s] = tanhf(p.y + biasS[d+1]);
        }
    }
    __syncthreads();

    // ---- C ----
    float rs0 = 0.f, rs1 = 0.f, rs2 = 0.f, rs3 = 0.f;
    for (int g = 0; g < 4; g++) {
        int s0 = g*64;
        {
            int ty = t >> 6;
            int tx = t & 63;
            u64 acc[4][4];
#pragma unroll
            for (int i = 0; i < 4; i++)
#pragma unroll
                for (int j = 0; j < 4; j++) acc[i][j] = 0ull;
#pragma unroll 4
            for (int e = 0; e < 64; e++) {
                const float* qe = &qT[e*QST];
                ulonglong2 a01 = *(const ulonglong2*)&qe[s0 + 8*ty];
                ulonglong2 a23 = *(const ulonglong2*)&qe[s0 + 8*ty + 4];
                float4 bf = *(const float4*)&qe[4*tx];
                u64 b0 = splat2(bf.x), b1 = splat2(bf.y), b2 = splat2(bf.z), b3 = splat2(bf.w);
                ffma2(acc[0][0], a01.x, b0); ffma2(acc[0][1], a01.x, b1);
                ffma2(acc[0][2], a01.x, b2); ffma2(acc[0][3], a01.x, b3);
                ffma2(acc[1][0], a01.y, b0); ffma2(acc[1][1], a01.y, b1);
                ffma2(acc[1][2], a01.y, b2); ffma2(acc[1][3], a01.y, b3);
                ffma2(acc[2][0], a23.x, b0); ffma2(acc[2][1], a23.x, b1);
                ffma2(acc[2][2], a23.x, b2); ffma2(acc[2][3], a23.x, b3);
                ffma2(acc[3][0], a23.y, b0); ffma2(acc[3][1], a23.y, b1);
                ffma2(acc[3][2], a23.y, b2); ffma2(acc[3][3], a23.y, b3);
            }
#pragma unroll
            for (int rp = 0; rp < 4; rp++) {
                float2 c0 = unpack2(acc[rp][0]), c1 = unpack2(acc[rp][1]);
                float2 c2 = unpack2(acc[rp][2]), c3 = unpack2(acc[rp][3]);
                *(float4*)&sc[(8*ty + 2*rp)*SST + 4*tx] =
                    make_float4(c0.x, c1.x, c2.x, c3.x);
                *(float4*)&sc[(8*ty + 2*rp + 1)*SST + 4*tx] =
                    make_float4(c0.y, c1.y, c2.y, c3.y);
            }
        }
        __syncthreads();
        // C2: masked row softmax — accurate expf (feeds seq -> mean -> logits -> idx)
        for (int rr = w; rr < 64; rr += 16) {
            int s = s0 + rr;
            if (maskS[s] == 0.f) {
                for (int c = l; c < 256; c += 32) sc[rr*SST + c] = 0.f;
            } else {
                float v[8]; float mx = FMIN2;
#pragma unroll
                for (int c = 0; c < 8; c++) {
                    float rawv = sc[rr*SST + l + 32*c] * 0.125f;
                    if (maskS[l + 32*c] == 0.f) rawv = NEGV;
                    v[c] = rawv; mx = fmaxf(mx, rawv);
                }
#pragma unroll
                for (int o = 16; o; o >>= 1) mx = fmaxf(mx, __shfl_xor_sync(~0u, mx, o));
                float sum = 0.f;
#pragma unroll
                for (int c = 0; c < 8; c++) { v[c] = expf(v[c] - mx); sum += v[c]; }
#pragma unroll
                for (int o = 16; o; o >>= 1) sum += __shfl_xor_sync(~0u, sum, o);
                float inv = 1.f / sum;
#pragma unroll
                for (int c = 0; c < 8; c++) sc[rr*SST + l + 32*c] = v[c]*inv;
            }
        }
        __syncthreads();
        {
            int ry = t >> 4;
            int rx = t & 15;
            u64 a00 = 0ull, a01v = 0ull, a10 = 0ull, a11 = 0ull;
            const float* r0p = &sc[(2*ry)*SST];
            const float* r1p = &sc[(2*ry + 1)*SST];
#pragma unroll 2
            for (int k = 0; k < 256; k += 2) {
                float2 af0 = *(const float2*)&r0p[k];
                float2 af1 = *(const float2*)&r1p[k];
                ulonglong2 bk  = *(const ulonglong2*)&itemsS[k*IST + 4*rx];
                ulonglong2 bk1 = *(const ulonglong2*)&itemsS[(k+1)*IST + 4*rx];
                u64 s00 = splat2(af0.x), s01 = splat2(af0.y);
                u64 s10 = splat2(af1.x), s11 = splat2(af1.y);
                ffma2(a00,  s00, bk.x);  ffma2(a01v, s00, bk.y);
                ffma2(a10,  s10, bk.x);  ffma2(a11,  s10, bk.y);
                ffma2(a00,  s01, bk1.x); ffma2(a01v, s01, bk1.y);
                ffma2(a10,  s11, bk1.x); ffma2(a11,  s11, bk1.y);
            }
            float2 u00 = unpack2(a00), u01 = unpack2(a01v);
            float2 u10 = unpack2(a10), u11 = unpack2(a11);
            float4 row0 = make_float4(u00.x, u00.y, u01.x, u01.y);
            float4 row1 = make_float4(u10.x, u10.y, u11.x, u11.y);
            float* so = &g_seq[((size_t)b*SS + s0 + 2*ry)*DD + 4*rx];
            *(float4*)so = row0;
            *(float4*)(so + DD) = row1;
            rs0 += row0.x + row1.x; rs1 += row0.y + row1.y;
            rs2 += row0.z + row1.z; rs3 += row0.w + row1.w;
        }
        __syncthreads();
    }
    {
        int rx = t & 15;
        atomicAdd(&colS[4*rx],   rs0);
        atomicAdd(&colS[4*rx+1], rs1);
        atomicAdd(&colS[4*rx+2], rs2);
        atomicAdd(&colS[4*rx+3], rs3);
    }
    // ---- mean_h, logits, logits@trans, top-4 (accurate path: tanhf, scalar fp32) ----
    float* W1S = sc; float* logitsS = sc + 4096; float* mhS = sc + 4608;
    float* wrS = sc + 4672; float* aqS = sc + 5712; float* uebS = sc + 5968;
    for (int i = t; i < 4096; i += 512) W1S[i] = W1[i];
    __syncthreads();
    if (t < 64) meanS[t] = (colS[t] + g_posSum[t]) * sDen;
    __syncthreads();
    if (t < 64) {
        float a = 0.f;
#pragma unroll 16
        for (int e = 0; e < 64; e++) a = fmaf(meanS[e], W1S[e*64 + t], a);
        mhS[t] = tanhf(a);
    }
    __syncthreads();
    {
        const float4* cr = (const float4*)&g_cand[(size_t)t*64];
        float a = 0.f;
#pragma unroll
        for (int e4 = 0; e4 < 16; e4++) {
            float4 cv = cr[e4];
            a = fmaf(cv.x, mhS[4*e4], a);   a = fmaf(cv.y, mhS[4*e4+1], a);
            a = fmaf(cv.z, mhS[4*e4+2], a); a = fmaf(cv.w, mhS[4*e4+3], a);
        }
        logitsS[t] = a;
    }
    __syncthreads();
    float lgv;
    {
        const float4* tr = (const float4*)&g_transT[(size_t)t*CC];
        float a = 0.f;
#pragma unroll 8
        for (int i4 = 0; i4 < 128; i4++) {
            float4 tv = tr[i4];
            a = fmaf(tv.x, logitsS[4*i4], a);   a = fmaf(tv.y, logitsS[4*i4+1], a);
            a = fmaf(tv.z, logitsS[4*i4+2], a); a = fmaf(tv.w, logitsS[4*i4+3], a);
        }
        lgv = a;
    }
    __syncthreads();
    logitsS[t] = lgv;
    __syncthreads();
    for (int p = 0; p < 4; p++) {
        float bv = logitsS[t]; int bi = t;
#pragma unroll
        for (int o = 16; o; o >>= 1) {
            float ov = __shfl_xor_sync(~0u, bv, o);
            int   oi = __shfl_xor_sync(~0u, bi, o);
            if (ov > bv || (ov == bv && oi < bi)) { bv = ov; bi = oi; }
        }
        if (l == 0) { rv[w] = bv; riS[w] = bi; }
        __syncthreads();
        if (t == 0) {
            float B2 = rv[0]; int BI = riS[0];
            for (int i = 1; i < 16; i++)
                if (rv[i] > B2 || (rv[i] == B2 && riS[i] < BI)) { B2 = rv[i]; BI = riS[i]; }
            idxS[p] = BI; logitsS[BI] = FMIN2;
        }
        __syncthreads();
    }
    if (t < 256) { int k = t >> 6, d = t & 63; aqS[t] = g_cand[(size_t)idxS[k]*64 + d]; }
    __syncthreads();

    // ---- D: multi-interest attention (fast math OK: feeds outputs 0/1 only) ----
    {
        int s = t >> 1, half = t & 1;
        int d0 = 32*half;
        u64 acc[16];
#pragma unroll
        for (int i = 0; i < 16; i++) acc[i] = 0ull;
        const float* sr = &g_seq[((size_t)b*SS + s)*DD];
#pragma unroll 4
        for (int e = 0; e < 64; e++) {
            float xe = sr[e] + pos[s*DD + e];
            u64 xs = splat2(xe);
            const ulonglong2* wp = (const ulonglong2*)&W1S[e*64 + d0];
#pragma unroll
            for (int q = 0; q < 8; q++) {
                ulonglong2 wv = wp[q];
                ffma2(acc[2*q],   xs, wv.x);
                ffma2(acc[2*q+1], xs, wv.y);
            }
        }
        float ihv[32];
#pragma unroll
        for (int i = 0; i < 16; i++) {
            float2 p = unpack2(acc[i]);
            ihv[2*i]   = tanh_fast(p.x);
            ihv[2*i+1] = tanh_fast(p.y);
        }
        float wv[4];
#pragma unroll
        for (int k = 0; k < 4; k++) {
            float a = 0.f;
            const float* aq = &aqS[k*64 + d0];
#pragma unroll
            for (int i = 0; i < 32; i++) a = fmaf(ihv[i], aq[i], a);
            a += __shfl_xor_sync(~0u, a, 1);
            wv[k] = a;
        }
        if (half == 0) {
            float m = maskS[s];
#pragma unroll
            for (int k = 0; k < 4; k++)
                wrS[k*260 + s] = (m == 0.f) ? NEGV : wv[k];
        }
    }
    __syncthreads();
    if (w < 4) {
        float v[8]; float mx = FMIN2;
#pragma unroll
        for (int c = 0; c < 8; c++) { v[c] = wrS[w*260 + l + 32*c]; mx = fmaxf(mx, v[c]); }
#pragma unroll
        for (int o = 16; o; o >>= 1) mx = fmaxf(mx, __shfl_xor_sync(~0u, mx, o));
        float sum = 0.f;
#pragma unroll
        for (int c = 0; c < 8; c++) { v[c] = __expf(v[c] - mx); sum += v[c]; }
#pragma unroll
        for (int o = 16; o; o >>= 1) sum += __shfl_xor_sync(~0u, sum, o);
        float inv = 1.f / sum;
#pragma unroll
        for (int c = 0; c < 8; c++) wrS[w*260 + l + 32*c] = v[c]*inv;
    }
    __syncthreads();
    if (t < 256) {
        int k = t >> 6, d = t & 63;
        const float* wp = &wrS[k*260];
        const float* sp = &g_seq[(size_t)b*SS*DD + d];
        float a = 0.f;
#pragma unroll 8
        for (int s = 0; s < 256; s++) a = fmaf(wp[s], sp[(size_t)s*64], a);
        uebS[t] = a;
        long off = 32768 + (long)b*256 + t;
        if (off < out_size) out[off] = a;
    }
    __syncthreads();
    if (w < 4) {
        float p = uebS[w*64 + l]*itemS[l] + uebS[w*64 + l + 32]*itemS[l + 32];
#pragma unroll
        for (int o = 16; o; o >>= 1) p += __shfl_xor_sync(~0u, p, o);
        if (l == 0) dotS[w] = p;
    }
    __syncthreads();
    if (t == 0) {
        float bv2 = dotS[0]; int bi2 = 0;
        for (int k = 1; k < 4; k++) if (dotS[k] > bv2) { bv2 = dotS[k]; bi2 = k; }
        ridxS = bi2;
    }
    __syncthreads();
    if (t < 64) {
        long off = (long)b*64 + t;
        if (off < out_size) out[off] = uebS[ridxS*64 + t];
    }
    if (t < 4) {
        long off = 163840 + (long)b*4 + t;
        if (off < out_size) out[off] = (float)idxS[t];
    }
}

extern "C" void kernel_launch(void* const* d_in, const int* in_sizes, int n_in,
                              void* d_out, int out_size) {
    const float* E    = (const float*)d_in[0];
    const float* W1   = (const float*)d_in[1];
    const float* W2   = (const float*)d_in[2];
    const float* W3   = (const float*)d_in[3];
    const float* W4   = (const float*)d_in[4];
    const float* pos  = (const float*)d_in[5];
    const float* dw   = (const float*)d_in[6];
    const float* db   = (const float*)d_in[7];
    const int*   his  = (const int*)d_in[8];
    const int*   mask = (const int*)d_in[9];
    const int*   midb = (const int*)d_in[10];
    float* out = (float*)d_out;

    cudaFuncSetAttribute(k_att, cudaFuncAttributeMaxDynamicSharedMemorySize,
                         SM_FLOATS * (int)sizeof(float));

    k_pre<<<1, 256>>>(pos);
    k_wmean<<<1184, 256>>>(E, W2);
    k_cand<<<CC, DD>>>(W3, W1, W4);
    k_trans<<<CC, 256>>>();
    k_att<<<BB, 512, SM_FLOATS * sizeof(float)>>>(E, W1, pos, dw, db,
                                                  his, mask, midb,
                                                  out, (long)out_size);
}